// round 13
// baseline (speedup 1.0000x reference)
#include <cuda_runtime.h>
#include <math.h>

// Shapes fixed by dataset: x [2,32,96,96] f32, aff [2,2,4,4] f32,
// out [2,32,96,96,96] f32.
constexpr int kB   = 2;
constexpr int kC   = 32;
constexpr int kSP  = 96;
constexpr int kNSL = 2;
constexpr int kCS  = kC / kNSL;   // 16
constexpr int kSP2 = kSP * kSP;   // 9216
constexpr int kSP3 = kSP * kSP2;  // 884736
constexpr int kMAXW = 6;          // max slab candidates per row
constexpr int kWIN  = 16;         // per-warp w-window for smem merge
constexpr int kTS   = 17;         // tile row stride (bank-conflict-free)
constexpr int kWPB  = 4;          // warps per block (fine-grained waves)

// ---------------------------------------------------------------------------
// theta = inv( aff * diag(1/zoom,1) )[:3,:]
// ---------------------------------------------------------------------------
__device__ __forceinline__ void compute_theta(const float* __restrict__ A,
                                              float* __restrict__ T) {
    float zoom[3];
#pragma unroll
    for (int j = 0; j < 3; j++) {
        float a0 = A[j], a1 = A[4 + j], a2 = A[8 + j];
        zoom[j] = sqrtf(a0 * a0 + a1 * a1 + a2 * a2);
    }
    float M[3][4];
#pragma unroll
    for (int i = 0; i < 3; i++)
#pragma unroll
        for (int j = 0; j < 4; j++) {
            float v = A[i * 4 + j];
            if (j < 3) v /= zoom[j];
            M[i][j] = v;
        }
    float a = M[0][0], b = M[0][1], c = M[0][2];
    float d = M[1][0], e = M[1][1], f = M[1][2];
    float g = M[2][0], h = M[2][1], i = M[2][2];
    float det = a * (e * i - f * h) - b * (d * i - f * g) + c * (d * h - e * g);
    float id  = 1.0f / det;
    float R00 = (e * i - f * h) * id, R01 = (c * h - b * i) * id, R02 = (b * f - c * e) * id;
    float R10 = (f * g - d * i) * id, R11 = (a * i - c * g) * id, R12 = (c * d - a * f) * id;
    float R20 = (d * h - e * g) * id, R21 = (b * g - a * h) * id, R22 = (a * e - b * d) * id;
    float tx = M[0][3], ty = M[1][3], tz = M[2][3];
    T[0] = R00; T[1] = R01; T[2]  = R02; T[3]  = -(R00 * tx + R01 * ty + R02 * tz);
    T[4] = R10; T[5] = R11; T[6]  = R12; T[7]  = -(R10 * tx + R11 * ty + R12 * tz);
    T[8] = R20; T[9] = R21; T[10] = R22; T[11] = -(R20 * tx + R21 * ty + R22 * tz);
}

// Exact per-voxel sample (identical math to the reference path).
__device__ __forceinline__ float sample_voxel(
    const float* __restrict__ T, const float* __restrict__ xc,
    float gxb, float gyb, float gzb, int w) {
    const float s = 2.0f / kSP;
    float xn = (w + 0.5f) * s - 1.0f;
    float gx = T[0] * xn + gxb;
    float ix = ((gx + 1.0f) * (float)kSP - 1.0f) * 0.5f;
    float fl = floorf(ix);
    float fx = ix - fl;
    float wx = (fl == 48.0f) ? (1.0f - fx) : ((fl == 47.0f) ? fx : 0.0f);
    if (wx <= 0.0f) return 0.0f;

    float gy = T[4] * xn + gyb;
    float gz = T[8] * xn + gzb;
    float iy = ((gy + 1.0f) * (float)kSP - 1.0f) * 0.5f;
    float iz = ((gz + 1.0f) * (float)kSP - 1.0f) * 0.5f;
    float fly = floorf(iy), flz = floorf(iz);
    float fy = iy - fly,    fz = iz - flz;
    int iy0 = (int)fly, iz0 = (int)flz;

    float acc = 0.0f;
#pragma unroll
    for (int k = 0; k < 4; k++) {
        int dy = k & 1, dz = k >> 1;
        int yy = iy0 + dy, zz = iz0 + dz;
        bool v = (yy >= 0) && (yy < kSP) && (zz >= 0) && (zz < kSP);
        float wv = (dz ? fz : 1.0f - fz) * (dy ? fy : 1.0f - fy) * wx;
        int yc = min(max(yy, 0), kSP - 1);
        int zc = min(max(zz, 0), kSP - 1);
        acc += (v ? wv : 0.0f) * __ldg(xc + zc * kSP + yc);
    }
    return acc;
}

// ---------------------------------------------------------------------------
// One warp owns 32 consecutive h-rows of one (b,ch,d) slice (12KB contiguous).
//   Phase A: lane L samples its row's slab values into a 32xkWIN smem tile.
//   Phase B: 24 coalesced streaming STG.128 (evict-first; write-once output).
//   Fallback (window too wide / degenerate affine): fill + fence + patch.
// 128-thread blocks (4 warps): 4608 blocks -> finer wave granularity over
// 148 SMs, smoother tail than 2304x256.
// ---------------------------------------------------------------------------
__global__ void __launch_bounds__(128, 16) skip_fused(
    const float* __restrict__ x, const float* __restrict__ aff,
    float* __restrict__ out) {

    int wid  = threadIdx.x >> 5;
    int lane = threadIdx.x & 31;
    int warp = blockIdx.x * kWPB + wid;

    int hg   = warp % 3;          // h-group: h0 = hg*32
    int rest = warp / 3;
    int c    = rest % kCS;
    rest    /= kCS;
    int d    = rest % kSP;
    int bs   = rest / kSP;        // b*kNSL + sl
    int b    = bs >> 1;
    int sl   = bs & 1;

    __shared__ float T[12];
    __shared__ float tile[kWPB][32 * kTS];
    if (threadIdx.x == 0)
        compute_theta(aff + (sl * kB + b) * 16, T);
    __syncthreads();

    int ch_global = b * kC + sl * kCS + c;
    int h0 = hg * 32;
    size_t base = (size_t)ch_global * kSP3 + (size_t)d * kSP2 + (size_t)h0 * kSP;
    const float* xc = x + (size_t)ch_global * kSP2;

    // ---- Per-lane row geometry (row h = h0 + lane) ----
    int h = h0 + lane;
    const float s = 2.0f / kSP;
    float yn = (h + 0.5f) * s - 1.0f;
    float zn = (d + 0.5f) * s - 1.0f;

    float gxb = T[1] * yn + T[2]  * zn + T[3];
    float gyb = T[5] * yn + T[6]  * zn + T[7];
    float gzb = T[9] * yn + T[10] * zn + T[11];

    // ix(w) = c1*w + c0, hit slab when ix in (47,49)
    float c1 = 48.0f * T[0] * s;
    float c0 = 48.0f * (T[0] * (0.5f * s - 1.0f) + gxb) + 47.5f;

    int wlo = 1, whi = 0;             // empty
    bool fallback = false;
    if (fabsf(c1) < 1e-7f) {
        if (c0 > 47.0f && c0 < 49.0f) { wlo = 0; whi = kSP - 1; fallback = true; }
    } else {
        float wa = (47.0f - c0) / c1;
        float wb = (49.0f - c0) / c1;
        float lo = fminf(wa, wb), hi = fmaxf(wa, wb);
        int l = max(0,       (int)floorf(lo) - 1);
        int r = min(kSP - 1, (int)floorf(hi) + 1);
        if (l <= r) {
            wlo = l; whi = r;
            if (r - l + 1 > kMAXW) fallback = true;
        }
    }
    bool empty = (wlo > whi);

    // ---- Warp aggregates: window + fallback decision ----
    const unsigned FULL = 0xffffffffu;
    int wmin = __reduce_min_sync(FULL, empty ? 0x7fffffff : wlo);
    int wmax = __reduce_max_sync(FULL, empty ? (int)0x80000000 : whi);
    bool have    = (wmin <= wmax);
    bool warp_fb = __any_sync(FULL, fallback) ||
                   (have && (wmax - wmin + 1 > kWIN));

    float4* o4 = reinterpret_cast<float4*>(out + base);
    float4 z = make_float4(0.f, 0.f, 0.f, 0.f);

    if (!warp_fb) {
        int wbase = have ? wmin : (1 << 20);   // sentinel -> no phase overlaps

        // ---- Phase A: stage samples straight into the tile ----
        float* trow = &tile[wid][lane * kTS];
#pragma unroll
        for (int j = 0; j < kWIN; j++) trow[j] = 0.0f;
        if (!empty) {
#pragma unroll
            for (int j = 0; j < kMAXW; j++) {
                int w = wlo + j;
                if (w <= whi)
                    trow[w - wbase] = sample_voxel(T, xc, gxb, gyb, gzb, w);
            }
        }
        __syncwarp();

        // ---- Phase B: period-3 phase-specialized merged streaming stores ----
        int  k0p[3];
        int  mkp[3];
#pragma unroll
        for (int p = 0; p < 3; p++) {
            int col = lane + 8 * p;
            if (col >= 24) col -= 24;
            if (col >= 24) col -= 24;
            int k0 = col * 4 - wbase;
            bool ov = (k0 + 3 >= 0) && (k0 <= kWIN - 1);
            int mask = 0;
#pragma unroll
            for (int j = 0; j < 4; j++)
                if (k0 + j >= 0 && k0 + j < kWIN) mask |= (1 << j);
            k0p[p] = k0; mkp[p] = ov ? mask : 0;
        }

        const float* tb = &tile[wid][0];
        int r = lane / 24;                     // row for i=0 (idx=lane)
        int m = lane - r * 24;                 // idx % 24
#pragma unroll
        for (int i = 0; i < 24; i++) {
            int p = i - (i / 3) * 3;           // i % 3, folds at compile time
            float4 v = z;
            if (mkp[p]) {
                const float* tr = tb + r * kTS + k0p[p];
                if (mkp[p] & 1) v.x = tr[0];
                if (mkp[p] & 2) v.y = tr[1];
                if (mkp[p] & 4) v.z = tr[2];
                if (mkp[p] & 8) v.w = tr[3];
            }
            __stcs(o4 + i * 32 + lane, v);     // streaming: evict-first in L2
            m += 8; r += 1;
            if (m >= 24) { m -= 24; r += 1; }
        }
    } else {
        // ---- Fallback: fill + fence + patch (recompute samples) ----
#pragma unroll
        for (int i = 0; i < 24; i++)
            __stcs(o4 + i * 32 + lane, z);
        __threadfence_block();
        __syncwarp();

        float* orow = out + base + (size_t)lane * kSP;
        for (int w = wlo; w <= whi; w++) {
            float v = sample_voxel(T, xc, gxb, gyb, gzb, w);
            if (v != 0.0f) orow[w] = v;
        }
    }
}

extern "C" void kernel_launch(void* const* d_in, const int* in_sizes, int n_in,
                              void* d_out, int out_size) {
    const float* x   = (const float*)d_in[0];
    const float* aff = (const float*)d_in[1];
    float* out       = (float*)d_out;

    // warps = kNSL*kB * kSP(d) * kCS(c) * 3(h-groups) = 18432 -> 4608 blocks
    const int warps = kNSL * kB * kSP * kCS * 3;
    skip_fused<<<warps / kWPB, 128>>>(x, aff, out);
}

// round 14
// speedup vs baseline: 1.0073x; 1.0073x over previous
#include <cuda_runtime.h>
#include <math.h>

// Shapes fixed by dataset: x [2,32,96,96] f32, aff [2,2,4,4] f32,
// out [2,32,96,96,96] f32.
//
// Structure of the problem: the reference builds a zero 96^3 volume with the
// 2D slice stack placed at W-plane 48, then trilinearly resamples through a
// near-identity affine. Only voxels whose sampled x-coordinate lands in
// (47,49) are nonzero (~2% slab); for those the trilinear sample degenerates
// to a 2D bilinear gather on x times an x-weight. The kernel is therefore a
// max-bandwidth streaming fill with the slab values merged into the store
// stream via a per-warp shared-memory tile. Measured floor: HBM/LTS write
// path (~6 TB/s effective), all SM-side units < 60%.
constexpr int kB   = 2;
constexpr int kC   = 32;
constexpr int kSP  = 96;
constexpr int kNSL = 2;
constexpr int kCS  = kC / kNSL;   // 16
constexpr int kSP2 = kSP * kSP;   // 9216
constexpr int kSP3 = kSP * kSP2;  // 884736
constexpr int kMAXW = 6;          // max slab candidates per row
constexpr int kWIN  = 16;         // per-warp w-window for smem merge
constexpr int kTS   = 17;         // tile row stride (bank-conflict-free)

// ---------------------------------------------------------------------------
// theta = inv( aff * diag(1/zoom,1) )[:3,:]
// ---------------------------------------------------------------------------
__device__ __forceinline__ void compute_theta(const float* __restrict__ A,
                                              float* __restrict__ T) {
    float zoom[3];
#pragma unroll
    for (int j = 0; j < 3; j++) {
        float a0 = A[j], a1 = A[4 + j], a2 = A[8 + j];
        zoom[j] = sqrtf(a0 * a0 + a1 * a1 + a2 * a2);
    }
    float M[3][4];
#pragma unroll
    for (int i = 0; i < 3; i++)
#pragma unroll
        for (int j = 0; j < 4; j++) {
            float v = A[i * 4 + j];
            if (j < 3) v /= zoom[j];
            M[i][j] = v;
        }
    float a = M[0][0], b = M[0][1], c = M[0][2];
    float d = M[1][0], e = M[1][1], f = M[1][2];
    float g = M[2][0], h = M[2][1], i = M[2][2];
    float det = a * (e * i - f * h) - b * (d * i - f * g) + c * (d * h - e * g);
    float id  = 1.0f / det;
    float R00 = (e * i - f * h) * id, R01 = (c * h - b * i) * id, R02 = (b * f - c * e) * id;
    float R10 = (f * g - d * i) * id, R11 = (a * i - c * g) * id, R12 = (c * d - a * f) * id;
    float R20 = (d * h - e * g) * id, R21 = (b * g - a * h) * id, R22 = (a * e - b * d) * id;
    float tx = M[0][3], ty = M[1][3], tz = M[2][3];
    T[0] = R00; T[1] = R01; T[2]  = R02; T[3]  = -(R00 * tx + R01 * ty + R02 * tz);
    T[4] = R10; T[5] = R11; T[6]  = R12; T[7]  = -(R10 * tx + R11 * ty + R12 * tz);
    T[8] = R20; T[9] = R21; T[10] = R22; T[11] = -(R20 * tx + R21 * ty + R22 * tz);
}

// Exact per-voxel sample (identical math to the reference path).
__device__ __forceinline__ float sample_voxel(
    const float* __restrict__ T, const float* __restrict__ xc,
    float gxb, float gyb, float gzb, int w) {
    const float s = 2.0f / kSP;
    float xn = (w + 0.5f) * s - 1.0f;
    float gx = T[0] * xn + gxb;
    float ix = ((gx + 1.0f) * (float)kSP - 1.0f) * 0.5f;
    float fl = floorf(ix);
    float fx = ix - fl;
    float wx = (fl == 48.0f) ? (1.0f - fx) : ((fl == 47.0f) ? fx : 0.0f);
    if (wx <= 0.0f) return 0.0f;

    float gy = T[4] * xn + gyb;
    float gz = T[8] * xn + gzb;
    float iy = ((gy + 1.0f) * (float)kSP - 1.0f) * 0.5f;
    float iz = ((gz + 1.0f) * (float)kSP - 1.0f) * 0.5f;
    float fly = floorf(iy), flz = floorf(iz);
    float fy = iy - fly,    fz = iz - flz;
    int iy0 = (int)fly, iz0 = (int)flz;

    float acc = 0.0f;
#pragma unroll
    for (int k = 0; k < 4; k++) {
        int dy = k & 1, dz = k >> 1;
        int yy = iy0 + dy, zz = iz0 + dz;
        bool v = (yy >= 0) && (yy < kSP) && (zz >= 0) && (zz < kSP);
        float wv = (dz ? fz : 1.0f - fz) * (dy ? fy : 1.0f - fy) * wx;
        int yc = min(max(yy, 0), kSP - 1);
        int zc = min(max(zz, 0), kSP - 1);
        acc += (v ? wv : 0.0f) * __ldg(xc + zc * kSP + yc);
    }
    return acc;
}

// ---------------------------------------------------------------------------
// One warp owns 32 consecutive h-rows of one (b,ch,d) slice (12KB contiguous).
//   Phase A: lane L samples its row's slab values into a 32xkWIN smem tile.
//   Phase B: 24 coalesced streaming STG.128 (evict-first; write-once output);
//            period-3 phase-specialized merge sources the tile only where the
//            warp's slab window overlaps. Every address written exactly once.
//   Fallback (window too wide / degenerate affine): fill + fence + patch.
// ---------------------------------------------------------------------------
__global__ void __launch_bounds__(256, 8) skip_fused(
    const float* __restrict__ x, const float* __restrict__ aff,
    float* __restrict__ out) {

    int wid  = threadIdx.x >> 5;
    int lane = threadIdx.x & 31;
    int warp = blockIdx.x * 8 + wid;

    int hg   = warp % 3;          // h-group: h0 = hg*32
    int rest = warp / 3;
    int c    = rest % kCS;
    rest    /= kCS;
    int d    = rest % kSP;
    int bs   = rest / kSP;        // b*kNSL + sl
    int b    = bs >> 1;
    int sl   = bs & 1;

    __shared__ float T[12];
    __shared__ float tile[8][32 * kTS];
    if (threadIdx.x == 0)
        compute_theta(aff + (sl * kB + b) * 16, T);
    __syncthreads();

    int ch_global = b * kC + sl * kCS + c;
    int h0 = hg * 32;
    size_t base = (size_t)ch_global * kSP3 + (size_t)d * kSP2 + (size_t)h0 * kSP;
    const float* xc = x + (size_t)ch_global * kSP2;

    // ---- Per-lane row geometry (row h = h0 + lane) ----
    int h = h0 + lane;
    const float s = 2.0f / kSP;
    float yn = (h + 0.5f) * s - 1.0f;
    float zn = (d + 0.5f) * s - 1.0f;

    float gxb = T[1] * yn + T[2]  * zn + T[3];
    float gyb = T[5] * yn + T[6]  * zn + T[7];
    float gzb = T[9] * yn + T[10] * zn + T[11];

    // ix(w) = c1*w + c0, hit slab when ix in (47,49)
    float c1 = 48.0f * T[0] * s;
    float c0 = 48.0f * (T[0] * (0.5f * s - 1.0f) + gxb) + 47.5f;

    int wlo = 1, whi = 0;             // empty
    bool fallback = false;
    if (fabsf(c1) < 1e-7f) {
        if (c0 > 47.0f && c0 < 49.0f) { wlo = 0; whi = kSP - 1; fallback = true; }
    } else {
        float wa = (47.0f - c0) / c1;
        float wb = (49.0f - c0) / c1;
        float lo = fminf(wa, wb), hi = fmaxf(wa, wb);
        int l = max(0,       (int)floorf(lo) - 1);
        int r = min(kSP - 1, (int)floorf(hi) + 1);
        if (l <= r) {
            wlo = l; whi = r;
            if (r - l + 1 > kMAXW) fallback = true;
        }
    }
    bool empty = (wlo > whi);

    // ---- Warp aggregates: window + fallback decision ----
    const unsigned FULL = 0xffffffffu;
    int wmin = __reduce_min_sync(FULL, empty ? 0x7fffffff : wlo);
    int wmax = __reduce_max_sync(FULL, empty ? (int)0x80000000 : whi);
    bool have    = (wmin <= wmax);
    bool warp_fb = __any_sync(FULL, fallback) ||
                   (have && (wmax - wmin + 1 > kWIN));

    float4* o4 = reinterpret_cast<float4*>(out + base);
    float4 z = make_float4(0.f, 0.f, 0.f, 0.f);

    if (!warp_fb) {
        int wbase = have ? wmin : (1 << 20);   // sentinel -> no phase overlaps

        // ---- Phase A: stage samples straight into the tile ----
        float* trow = &tile[wid][lane * kTS];
#pragma unroll
        for (int j = 0; j < kWIN; j++) trow[j] = 0.0f;
        if (!empty) {
#pragma unroll
            for (int j = 0; j < kMAXW; j++) {
                int w = wlo + j;
                if (w <= whi)
                    trow[w - wbase] = sample_voxel(T, xc, gxb, gyb, gzb, w);
            }
        }
        __syncwarp();

        // ---- Phase B: period-3 phase-specialized merged streaming stores ----
        // idx = i*32+lane; column = (lane + 8*(i%3)) % 24; row = idx/24.
        int  k0p[3];
        int  mkp[3];
#pragma unroll
        for (int p = 0; p < 3; p++) {
            int col = lane + 8 * p;
            if (col >= 24) col -= 24;
            if (col >= 24) col -= 24;
            int k0 = col * 4 - wbase;
            bool ov = (k0 + 3 >= 0) && (k0 <= kWIN - 1);
            int mask = 0;
#pragma unroll
            for (int j = 0; j < 4; j++)
                if (k0 + j >= 0 && k0 + j < kWIN) mask |= (1 << j);
            k0p[p] = k0; mkp[p] = ov ? mask : 0;
        }

        const float* tb = &tile[wid][0];
        int r = lane / 24;                     // row for i=0 (idx=lane)
        int m = lane - r * 24;                 // idx % 24
#pragma unroll
        for (int i = 0; i < 24; i++) {
            int p = i - (i / 3) * 3;           // i % 3, folds at compile time
            float4 v = z;
            if (mkp[p]) {
                const float* tr = tb + r * kTS + k0p[p];
                if (mkp[p] & 1) v.x = tr[0];
                if (mkp[p] & 2) v.y = tr[1];
                if (mkp[p] & 4) v.z = tr[2];
                if (mkp[p] & 8) v.w = tr[3];
            }
            __stcs(o4 + i * 32 + lane, v);     // streaming: evict-first in L2
            m += 8; r += 1;
            if (m >= 24) { m -= 24; r += 1; }
        }
    } else {
        // ---- Fallback: fill + fence + patch (recompute samples) ----
#pragma unroll
        for (int i = 0; i < 24; i++)
            __stcs(o4 + i * 32 + lane, z);
        __threadfence_block();
        __syncwarp();

        float* orow = out + base + (size_t)lane * kSP;
        for (int w = wlo; w <= whi; w++) {
            float v = sample_voxel(T, xc, gxb, gyb, gzb, w);
            if (v != 0.0f) orow[w] = v;
        }
    }
}

extern "C" void kernel_launch(void* const* d_in, const int* in_sizes, int n_in,
                              void* d_out, int out_size) {
    const float* x   = (const float*)d_in[0];
    const float* aff = (const float*)d_in[1];
    float* out       = (float*)d_out;

    // warps = kNSL*kB * kSP(d) * kCS(c) * 3(h-groups) = 18432 -> 2304 blocks
    const int warps = kNSL * kB * kSP * kCS * 3;
    skip_fused<<<warps / 8, 256>>>(x, aff, out);
}